// round 4
// baseline (speedup 1.0000x reference)
#include <cuda_runtime.h>
#include <cstdint>

#define BATCH 8
#define SEQ   1024
#define DIM   768
#define EPS_F 1e-7f

#define BM 128
#define BN 256
#define BK 16
#define PADK 20          // padded k-stride (floats): conflict-free frag loads

// Scratch (allocation-free rule: __device__ globals)
__device__ float g_E[(size_t)BATCH * SEQ * SEQ];        // exp(QK^T)*mask
__device__ float g_partial[(size_t)BATCH * SEQ * 16];   // per-(row, colslice)
__device__ float g_den[(size_t)BATCH * SEQ];

// fp32 -> tf32 round-to-nearest (unbiased)
__device__ __forceinline__ uint32_t f2tf(float x) {
    uint32_t u; asm("cvt.rna.tf32.f32 %0, %1;" : "=r"(u) : "f"(x)); return u;
}

__device__ __forceinline__ void mma_tf32(float c[4],
                                         uint32_t a0, uint32_t a1, uint32_t a2, uint32_t a3,
                                         uint32_t b0, uint32_t b1) {
    asm("mma.sync.aligned.m16n8k8.row.col.f32.tf32.tf32.f32 "
        "{%0,%1,%2,%3}, {%4,%5,%6,%7}, {%8,%9}, {%0,%1,%2,%3};"
        : "+f"(c[0]), "+f"(c[1]), "+f"(c[2]), "+f"(c[3])
        : "r"(a0), "r"(a1), "r"(a2), "r"(a3), "r"(b0), "r"(b1));
}

__device__ __forceinline__ uint4 cvt4(float4 v) {
    return make_uint4(f2tf(v.x), f2tf(v.y), f2tf(v.z), f2tf(v.w));
}

// ---------------------------------------------------------------------------
// Compute core: block 128x256, 8 warps (2x4), each warp 64x64 (4x8 m16n8).
// ---------------------------------------------------------------------------
#define COMPUTE_TILE(AsBuf, BsBuf)                                            \
    _Pragma("unroll")                                                         \
    for (int ks = 0; ks < 2; ks++) {                                          \
        uint32_t bf[8][2];                                                    \
        _Pragma("unroll")                                                     \
        for (int nt = 0; nt < 8; nt++) {                                      \
            int bb = (nBase + nt * 8 + qid) * PADK + ks * 8 + tq;             \
            bf[nt][0] = (BsBuf)[bb];                                          \
            bf[nt][1] = (BsBuf)[bb + 4];                                      \
        }                                                                     \
        _Pragma("unroll")                                                     \
        for (int mt = 0; mt < 4; mt++) {                                      \
            int ab = (mBase + mt * 16 + qid) * PADK + ks * 8 + tq;            \
            uint32_t a0 = (AsBuf)[ab];                                        \
            uint32_t a1 = (AsBuf)[ab + 8 * PADK];                             \
            uint32_t a2 = (AsBuf)[ab + 4];                                    \
            uint32_t a3 = (AsBuf)[ab + 8 * PADK + 4];                         \
            _Pragma("unroll")                                                 \
            for (int nt = 0; nt < 8; nt++)                                    \
                mma_tf32(acc[mt][nt], a0, a1, a2, a3, bf[nt][0], bf[nt][1]);  \
        }                                                                     \
    }

#define SMEM_BYTES (2 * (BM + BN) * PADK * 4)   // 61440

// ---------------------------------------------------------------------------
// Kernel 1: E = exp(A A^T) * m_row * m_col, plus partial row sums.
// ---------------------------------------------------------------------------
__global__ void __launch_bounds__(256, 1) qk_exp_mma(const float* __restrict__ A,
                                                     const int*   __restrict__ mask)
{
    extern __shared__ uint32_t dsm[];
    uint32_t* As = dsm;                       // [2][BM*PADK]
    uint32_t* Bs = dsm + 2 * BM * PADK;       // [2][BN*PADK]

    const int b       = blockIdx.z;
    const int rowBase = blockIdx.y * BM;
    const int colBase = blockIdx.x * BN;
    const float* Ab = A + (size_t)b * SEQ * DIM;
    const int bS = b * SEQ;

    const int tid  = threadIdx.x;
    const int wid  = tid >> 5;
    const int lane = tid & 31;
    const int qid  = lane >> 2;   // 0..7
    const int tq   = lane & 3;    // 0..3
    const int mBase = (wid >> 2) * 64;
    const int nBase = (wid & 3) * 64;

    const int r_ld  = tid >> 2;           // 0..63
    const int c4_ld = (tid & 3) << 2;     // 0,4,8,12

    float acc[4][8][4];
    #pragma unroll
    for (int i = 0; i < 4; i++)
        #pragma unroll
        for (int j = 0; j < 8; j++)
            #pragma unroll
            for (int k = 0; k < 4; k++) acc[i][j][k] = 0.f;

    const int NT = DIM / BK;   // 48

    // prologue: tile 0
    #pragma unroll
    for (int l = 0; l < 2; l++) {
        int r = r_ld + l * 64;
        float4 va = *(const float4*)(Ab + (size_t)(rowBase + r) * DIM + c4_ld);
        *(uint4*)&As[r * PADK + c4_ld] = cvt4(va);
    }
    #pragma unroll
    for (int l = 0; l < 4; l++) {
        int r = r_ld + l * 64;
        float4 vb = *(const float4*)(Ab + (size_t)(colBase + r) * DIM + c4_ld);
        *(uint4*)&Bs[r * PADK + c4_ld] = cvt4(vb);
    }
    __syncthreads();

    for (int it = 0; it < NT; it++) {
        const int buf = it & 1;
        float4 pA[2], pB[4];
        if (it + 1 < NT) {
            const int k0 = (it + 1) * BK;
            #pragma unroll
            for (int l = 0; l < 2; l++)
                pA[l] = *(const float4*)(Ab + (size_t)(rowBase + r_ld + l * 64) * DIM + k0 + c4_ld);
            #pragma unroll
            for (int l = 0; l < 4; l++)
                pB[l] = *(const float4*)(Ab + (size_t)(colBase + r_ld + l * 64) * DIM + k0 + c4_ld);
        }

        COMPUTE_TILE(As + buf * BM * PADK, Bs + buf * BN * PADK);

        if (it + 1 < NT) {
            uint32_t* An = As + (buf ^ 1) * BM * PADK;
            uint32_t* Bn = Bs + (buf ^ 1) * BN * PADK;
            #pragma unroll
            for (int l = 0; l < 2; l++)
                *(uint4*)&An[(r_ld + l * 64) * PADK + c4_ld] = cvt4(pA[l]);
            #pragma unroll
            for (int l = 0; l < 4; l++)
                *(uint4*)&Bn[(r_ld + l * 64) * PADK + c4_ld] = cvt4(pB[l]);
        }
        __syncthreads();
    }

    // Epilogue: exp * masks, store E, deterministic partial row sums.
    const int wc = wid & 3;
    #pragma unroll
    for (int mt = 0; mt < 4; mt++) {
        const int r0 = rowBase + mBase + mt * 16 + qid;
        const float mr0 = (float)mask[bS + r0];
        const float mr1 = (float)mask[bS + r0 + 8];
        float s0 = 0.f, s1 = 0.f;
        #pragma unroll
        for (int nt = 0; nt < 8; nt++) {
            const int cc = colBase + nBase + nt * 8 + tq * 2;
            const float mc0 = (float)mask[bS + cc];
            const float mc1 = (float)mask[bS + cc + 1];
            float e00 = __expf(acc[mt][nt][0]) * mr0 * mc0;
            float e01 = __expf(acc[mt][nt][1]) * mr0 * mc1;
            float e10 = __expf(acc[mt][nt][2]) * mr1 * mc0;
            float e11 = __expf(acc[mt][nt][3]) * mr1 * mc1;
            s0 += e00 + e01;
            s1 += e10 + e11;
            *(float2*)&g_E[((size_t)bS + r0) * SEQ + cc]     = make_float2(e00, e01);
            *(float2*)&g_E[((size_t)bS + r0 + 8) * SEQ + cc] = make_float2(e10, e11);
        }
        s0 += __shfl_xor_sync(0xffffffffu, s0, 1);
        s0 += __shfl_xor_sync(0xffffffffu, s0, 2);
        s1 += __shfl_xor_sync(0xffffffffu, s1, 1);
        s1 += __shfl_xor_sync(0xffffffffu, s1, 2);
        if (tq == 0) {
            g_partial[((size_t)bS + r0) * 16 + blockIdx.x * 4 + wc]     = s0;
            g_partial[((size_t)bS + r0 + 8) * 16 + blockIdx.x * 4 + wc] = s1;
        }
    }
}

// ---------------------------------------------------------------------------
// Kernel 2: deterministic denominator reduction.
// ---------------------------------------------------------------------------
__global__ void reduce_den_kernel()
{
    int i = blockIdx.x * blockDim.x + threadIdx.x;
    if (i < BATCH * SEQ) {
        float s = EPS_F;
        #pragma unroll
        for (int j = 0; j < 16; j++) s += g_partial[(size_t)i * 16 + j];
        g_den[i] = s;
    }
}

// ---------------------------------------------------------------------------
// Kernel 3: out = (E @ A) / den.
// ---------------------------------------------------------------------------
__global__ void __launch_bounds__(256, 1) pv_mma(const float* __restrict__ A,
                                                 float* __restrict__ out)
{
    extern __shared__ uint32_t dsm[];
    uint32_t* Es = dsm;
    uint32_t* Vs = dsm + 2 * BM * PADK;

    const int b       = blockIdx.z;
    const int rowBase = blockIdx.y * BM;   // S rows
    const int colBase = blockIdx.x * BN;   // D cols
    const float* Ab = A   + (size_t)b * SEQ * DIM;
    const float* Eb = g_E + (size_t)b * SEQ * SEQ;
    const int bS = b * SEQ;

    const int tid  = threadIdx.x;
    const int wid  = tid >> 5;
    const int lane = tid & 31;
    const int qid  = lane >> 2;
    const int tq   = lane & 3;
    const int mBase = (wid >> 2) * 64;
    const int nBase = (wid & 3) * 64;

    const int r_ld  = tid >> 2;
    const int c4_ld = (tid & 3) << 2;
    const int kk_ld = tid & 15;            // 0..15 (V transpose load)
    const int n4_ld = (tid >> 4) << 2;     // 0..60

    float acc[4][8][4];
    #pragma unroll
    for (int i = 0; i < 4; i++)
        #pragma unroll
        for (int j = 0; j < 8; j++)
            #pragma unroll
            for (int k = 0; k < 4; k++) acc[i][j][k] = 0.f;

    const int NT = SEQ / BK;   // 64

    // prologue
    #pragma unroll
    for (int l = 0; l < 2; l++) {
        int r = r_ld + l * 64;
        float4 ve = *(const float4*)(Eb + (size_t)(rowBase + r) * SEQ + c4_ld);
        *(uint4*)&Es[r * PADK + c4_ld] = cvt4(ve);
    }
    #pragma unroll
    for (int l = 0; l < 4; l++) {
        int n4 = n4_ld + l * 64;
        float4 vv = *(const float4*)(Ab + (size_t)kk_ld * DIM + colBase + n4);
        Vs[(n4 + 0) * PADK + kk_ld] = f2tf(vv.x);
        Vs[(n4 + 1) * PADK + kk_ld] = f2tf(vv.y);
        Vs[(n4 + 2) * PADK + kk_ld] = f2tf(vv.z);
        Vs[(n4 + 3) * PADK + kk_ld] = f2tf(vv.w);
    }
    __syncthreads();

    for (int it = 0; it < NT; it++) {
        const int buf = it & 1;
        float4 pE[2], pV[4];
        if (it + 1 < NT) {
            const int k0 = (it + 1) * BK;
            #pragma unroll
            for (int l = 0; l < 2; l++)
                pE[l] = *(const float4*)(Eb + (size_t)(rowBase + r_ld + l * 64) * SEQ + k0 + c4_ld);
            #pragma unroll
            for (int l = 0; l < 4; l++)
                pV[l] = *(const float4*)(Ab + (size_t)(k0 + kk_ld) * DIM + colBase + n4_ld + l * 64);
        }

        COMPUTE_TILE(Es + buf * BM * PADK, Vs + buf * BN * PADK);

        if (it + 1 < NT) {
            uint32_t* En = Es + (buf ^ 1) * BM * PADK;
            uint32_t* Vn = Vs + (buf ^ 1) * BN * PADK;
            #pragma unroll
            for (int l = 0; l < 2; l++)
                *(uint4*)&En[(r_ld + l * 64) * PADK + c4_ld] = cvt4(pE[l]);
            #pragma unroll
            for (int l = 0; l < 4; l++) {
                int n4 = n4_ld + l * 64;
                Vn[(n4 + 0) * PADK + kk_ld] = f2tf(pV[l].x);
                Vn[(n4 + 1) * PADK + kk_ld] = f2tf(pV[l].y);
                Vn[(n4 + 2) * PADK + kk_ld] = f2tf(pV[l].z);
                Vn[(n4 + 3) * PADK + kk_ld] = f2tf(pV[l].w);
            }
        }
        __syncthreads();
    }

    // Epilogue: scale by 1/den, store.
    #pragma unroll
    for (int mt = 0; mt < 4; mt++) {
        const int r0 = rowBase + mBase + mt * 16 + qid;
        const float inv0 = 1.0f / g_den[bS + r0];
        const float inv1 = 1.0f / g_den[bS + r0 + 8];
        #pragma unroll
        for (int nt = 0; nt < 8; nt++) {
            const int cc = colBase + nBase + nt * 8 + tq * 2;
            *(float2*)&out[((size_t)bS + r0) * DIM + cc] =
                make_float2(acc[mt][nt][0] * inv0, acc[mt][nt][1] * inv0);
            *(float2*)&out[((size_t)bS + r0 + 8) * DIM + cc] =
                make_float2(acc[mt][nt][2] * inv1, acc[mt][nt][3] * inv1);
        }
    }
}

// ---------------------------------------------------------------------------
extern "C" void kernel_launch(void* const* d_in, const int* in_sizes, int n_in,
                              void* d_out, int out_size)
{
    const float* A    = (const float*)d_in[0];
    const int*   mask = (const int*)d_in[1];
    float*       out  = (float*)d_out;

    static int configured = 0;
    if (!configured) {
        cudaFuncSetAttribute(qk_exp_mma, cudaFuncAttributeMaxDynamicSharedMemorySize, SMEM_BYTES);
        cudaFuncSetAttribute(pv_mma,     cudaFuncAttributeMaxDynamicSharedMemorySize, SMEM_BYTES);
        configured = 1;
    }

    dim3 g1(SEQ / BN, SEQ / BM, BATCH);   // 4 x 8 x 8 = 256
    qk_exp_mma<<<g1, 256, SMEM_BYTES>>>(A, mask);

    reduce_den_kernel<<<(BATCH * SEQ + 255) / 256, 256>>>();

    dim3 g2(DIM / BN, SEQ / BM, BATCH);   // 3 x 8 x 8 = 192
    pv_mma<<<g2, 256, SMEM_BYTES>>>(A, out);
}

// round 5
// speedup vs baseline: 1.4861x; 1.4861x over previous
#include <cuda_runtime.h>
#include <cstdint>

#define BATCH 8
#define SEQ   1024
#define DIM   768
#define EPS_F 1e-7f

#define BM 128
#define BN 128
#define BK 16
#define PADK 20      // K-major padded k-stride (floats)
#define PADN 136     // N-major padded n-stride (floats): conflict-free V frags
#define STAGES 3

// qk stage: As[128*PADK] + Bs[128*PADK]
#define QK_STAGE_F (2 * BM * PADK)                 // 5120 floats
#define QK_SMEM    (STAGES * QK_STAGE_F * 4)       // 61440 B
// pv stage: Es[128*PADK] + Vs[16*PADN]
#define PV_STAGE_F (BM * PADK + BK * PADN)         // 4736 floats
#define PV_SMEM    (STAGES * PV_STAGE_F * 4)       // 56832 B

// Scratch (allocation-free rule: __device__ globals)
__device__ float g_E[(size_t)BATCH * SEQ * SEQ];
__device__ float g_partial[(size_t)BATCH * SEQ * 32];
__device__ float g_den[(size_t)BATCH * SEQ];

__device__ __forceinline__ uint32_t smem_u32(const void* p) {
    uint32_t a;
    asm("{ .reg .u64 t; cvta.to.shared.u64 t, %1; cvt.u32.u64 %0, t; }" : "=r"(a) : "l"(p));
    return a;
}
__device__ __forceinline__ uint32_t f2tf(float x) {
    uint32_t u; asm("cvt.rna.tf32.f32 %0, %1;" : "=r"(u) : "f"(x)); return u;
}
__device__ __forceinline__ void mma_tf32(float c[4],
                                         uint32_t a0, uint32_t a1, uint32_t a2, uint32_t a3,
                                         uint32_t b0, uint32_t b1) {
    asm("mma.sync.aligned.m16n8k8.row.col.f32.tf32.tf32.f32 "
        "{%0,%1,%2,%3}, {%4,%5,%6,%7}, {%8,%9}, {%0,%1,%2,%3};"
        : "+f"(c[0]), "+f"(c[1]), "+f"(c[2]), "+f"(c[3])
        : "r"(a0), "r"(a1), "r"(a2), "r"(a3), "r"(b0), "r"(b1));
}
__device__ __forceinline__ void cp16(uint32_t saddr, const void* g) {
    asm volatile("cp.async.cg.shared.global [%0], [%1], 16;" :: "r"(saddr), "l"(g));
}
#define CP_COMMIT() asm volatile("cp.async.commit_group;" ::: "memory")
#define CP_WAIT1()  asm volatile("cp.async.wait_group 1;" ::: "memory")

// ---------------------------------------------------------------------------
// Compute cores: block 128x128, 8 warps (2x4), warp tile 64x32 (4x4 m16n8).
// A/E from K-major [row][PADK]; B from K-major (qk) or N-major [k][PADN] (pv).
// ---------------------------------------------------------------------------
#define COMPUTE_KM(AsBuf, BsBuf)                                              \
    _Pragma("unroll")                                                         \
    for (int ks = 0; ks < 2; ks++) {                                          \
        uint32_t bf[4][2];                                                    \
        _Pragma("unroll")                                                     \
        for (int nt = 0; nt < 4; nt++) {                                      \
            const float* bp = (BsBuf) + (nBase + nt * 8 + qid) * PADK + ks * 8 + tq; \
            bf[nt][0] = f2tf(bp[0]); bf[nt][1] = f2tf(bp[4]);                 \
        }                                                                     \
        _Pragma("unroll")                                                     \
        for (int mt = 0; mt < 4; mt++) {                                      \
            const float* ap = (AsBuf) + (mBase + mt * 16 + qid) * PADK + ks * 8 + tq; \
            uint32_t a0 = f2tf(ap[0]);                                        \
            uint32_t a1 = f2tf(ap[8 * PADK]);                                 \
            uint32_t a2 = f2tf(ap[4]);                                        \
            uint32_t a3 = f2tf(ap[8 * PADK + 4]);                             \
            _Pragma("unroll")                                                 \
            for (int nt = 0; nt < 4; nt++)                                    \
                mma_tf32(acc[mt][nt], a0, a1, a2, a3, bf[nt][0], bf[nt][1]);  \
        }                                                                     \
    }

#define COMPUTE_NM(AsBuf, VsBuf)                                              \
    _Pragma("unroll")                                                         \
    for (int ks = 0; ks < 2; ks++) {                                          \
        uint32_t bf[4][2];                                                    \
        _Pragma("unroll")                                                     \
        for (int nt = 0; nt < 4; nt++) {                                      \
            const float* bp = (VsBuf) + (ks * 8 + tq) * PADN + nBase + nt * 8 + qid; \
            bf[nt][0] = f2tf(bp[0]); bf[nt][1] = f2tf(bp[4 * PADN]);          \
        }                                                                     \
        _Pragma("unroll")                                                     \
        for (int mt = 0; mt < 4; mt++) {                                      \
            const float* ap = (AsBuf) + (mBase + mt * 16 + qid) * PADK + ks * 8 + tq; \
            uint32_t a0 = f2tf(ap[0]);                                        \
            uint32_t a1 = f2tf(ap[8 * PADK]);                                 \
            uint32_t a2 = f2tf(ap[4]);                                        \
            uint32_t a3 = f2tf(ap[8 * PADK + 4]);                             \
            _Pragma("unroll")                                                 \
            for (int nt = 0; nt < 4; nt++)                                    \
                mma_tf32(acc[mt][nt], a0, a1, a2, a3, bf[nt][0], bf[nt][1]);  \
        }                                                                     \
    }

// ---------------------------------------------------------------------------
// Kernel 1: E = exp(A A^T) * m_row * m_col + partial row sums.
// ---------------------------------------------------------------------------
__global__ void __launch_bounds__(256, 2) qk_exp_mma(const float* __restrict__ A,
                                                     const int*   __restrict__ mask)
{
    extern __shared__ float dsm[];

    const int b       = blockIdx.z;
    const int rowBase = blockIdx.y * BM;
    const int colBase = blockIdx.x * BN;
    const float* Ab = A + (size_t)b * SEQ * DIM;
    const int bS = b * SEQ;

    const int tid  = threadIdx.x;
    const int wid  = tid >> 5;
    const int lane = tid & 31;
    const int qid  = lane >> 2;
    const int tq   = lane & 3;
    const int mBase = (wid >> 2) * 64;
    const int nBase = (wid & 3) * 32;

    // loader mapping: rows r0, r0+64; 16B column chunk c4
    const int r0  = tid >> 2;
    const int c4  = (tid & 3) << 2;
    const float* gA0 = Ab + (size_t)(rowBase + r0) * DIM + c4;
    const float* gA1 = gA0 + (size_t)64 * DIM;
    const float* gB0 = Ab + (size_t)(colBase + r0) * DIM + c4;
    const float* gB1 = gB0 + (size_t)64 * DIM;
    const uint32_t sb  = smem_u32(dsm);
    const uint32_t sA0 = sb + (r0 * PADK + c4) * 4;
    const uint32_t sA1 = sb + ((r0 + 64) * PADK + c4) * 4;
    const uint32_t sB0 = sb + (BM * PADK + r0 * PADK + c4) * 4;
    const uint32_t sB1 = sb + (BM * PADK + (r0 + 64) * PADK + c4) * 4;

    float acc[4][4][4];
    #pragma unroll
    for (int i = 0; i < 4; i++)
        #pragma unroll
        for (int j = 0; j < 4; j++)
            #pragma unroll
            for (int k = 0; k < 4; k++) acc[i][j][k] = 0.f;

    const int NT = DIM / BK;   // 48

    #pragma unroll
    for (int s = 0; s < STAGES - 1; s++) {   // tiles 0,1
        const uint32_t so = s * QK_STAGE_F * 4;
        const int k0 = s * BK;
        cp16(sA0 + so, gA0 + k0); cp16(sA1 + so, gA1 + k0);
        cp16(sB0 + so, gB0 + k0); cp16(sB1 + so, gB1 + k0);
        CP_COMMIT();
    }

    for (int it = 0; it < NT; it++) {
        CP_WAIT1();
        __syncthreads();
        {   // issue tile it+2 into freed stage
            const int tn = it + 2;
            if (tn < NT) {
                const uint32_t so = (tn % STAGES) * QK_STAGE_F * 4;
                const int k0 = tn * BK;
                cp16(sA0 + so, gA0 + k0); cp16(sA1 + so, gA1 + k0);
                cp16(sB0 + so, gB0 + k0); cp16(sB1 + so, gB1 + k0);
            }
            CP_COMMIT();
        }
        const float* As = dsm + (it % STAGES) * QK_STAGE_F;
        const float* Bs = As + BM * PADK;
        COMPUTE_KM(As, Bs);
    }

    // Epilogue
    const int wc = wid & 3;
    #pragma unroll
    for (int mt = 0; mt < 4; mt++) {
        const int rr = rowBase + mBase + mt * 16 + qid;
        const float mr0 = (float)mask[bS + rr];
        const float mr1 = (float)mask[bS + rr + 8];
        float s0 = 0.f, s1 = 0.f;
        #pragma unroll
        for (int nt = 0; nt < 4; nt++) {
            const int cc = colBase + nBase + nt * 8 + tq * 2;
            const float mc0 = (float)mask[bS + cc];
            const float mc1 = (float)mask[bS + cc + 1];
            float e00 = __expf(acc[mt][nt][0]) * mr0 * mc0;
            float e01 = __expf(acc[mt][nt][1]) * mr0 * mc1;
            float e10 = __expf(acc[mt][nt][2]) * mr1 * mc0;
            float e11 = __expf(acc[mt][nt][3]) * mr1 * mc1;
            s0 += e00 + e01;
            s1 += e10 + e11;
            *(float2*)&g_E[((size_t)bS + rr) * SEQ + cc]     = make_float2(e00, e01);
            *(float2*)&g_E[((size_t)bS + rr + 8) * SEQ + cc] = make_float2(e10, e11);
        }
        s0 += __shfl_xor_sync(0xffffffffu, s0, 1);
        s0 += __shfl_xor_sync(0xffffffffu, s0, 2);
        s1 += __shfl_xor_sync(0xffffffffu, s1, 1);
        s1 += __shfl_xor_sync(0xffffffffu, s1, 2);
        if (tq == 0) {
            g_partial[((size_t)bS + rr) * 32 + blockIdx.x * 4 + wc]     = s0;
            g_partial[((size_t)bS + rr + 8) * 32 + blockIdx.x * 4 + wc] = s1;
        }
    }
}

// ---------------------------------------------------------------------------
__global__ void reduce_den_kernel()
{
    int i = blockIdx.x * blockDim.x + threadIdx.x;
    if (i < BATCH * SEQ) {
        float s = EPS_F;
        #pragma unroll
        for (int j = 0; j < 32; j++) s += g_partial[(size_t)i * 32 + j];
        g_den[i] = s;
    }
}

// ---------------------------------------------------------------------------
// Kernel 3: out = (E @ A) / den.  V stage is [k][n] (no transpose needed).
// ---------------------------------------------------------------------------
__global__ void __launch_bounds__(256, 2) pv_mma(const float* __restrict__ A,
                                                 float* __restrict__ out)
{
    extern __shared__ float dsm[];

    const int b       = blockIdx.z;
    const int rowBase = blockIdx.y * BM;   // S rows
    const int colBase = blockIdx.x * BN;   // D cols
    const float* Ab = A   + (size_t)b * SEQ * DIM;
    const float* Eb = g_E + (size_t)b * SEQ * SEQ;
    const int bS = b * SEQ;

    const int tid  = threadIdx.x;
    const int wid  = tid >> 5;
    const int lane = tid & 31;
    const int qid  = lane >> 2;
    const int tq   = lane & 3;
    const int mBase = (wid >> 2) * 64;
    const int nBase = (wid & 3) * 32;

    // E loader: rows r0, r0+64, chunk c4
    const int r0  = tid >> 2;
    const int c4  = (tid & 3) << 2;
    const float* gE0 = Eb + (size_t)(rowBase + r0) * SEQ + c4;
    const float* gE1 = gE0 + (size_t)64 * SEQ;
    // V loader: [16][128] tile = 512 chunks; vid = tid, tid+256
    const int vr0  = tid >> 5;             // 0..7
    const int vc4  = (tid & 31) << 2;      // 0..124
    const float* gV0 = Ab + (size_t)vr0 * DIM + colBase + vc4;
    const float* gV1 = gV0 + (size_t)8 * DIM;

    const uint32_t sb  = smem_u32(dsm);
    const uint32_t sE0 = sb + (r0 * PADK + c4) * 4;
    const uint32_t sE1 = sb + ((r0 + 64) * PADK + c4) * 4;
    const uint32_t sV0 = sb + (BM * PADK + vr0 * PADN + vc4) * 4;
    const uint32_t sV1 = sb + (BM * PADK + (vr0 + 8) * PADN + vc4) * 4;

    float acc[4][4][4];
    #pragma unroll
    for (int i = 0; i < 4; i++)
        #pragma unroll
        for (int j = 0; j < 4; j++)
            #pragma unroll
            for (int k = 0; k < 4; k++) acc[i][j][k] = 0.f;

    const int NT = SEQ / BK;   // 64

    #pragma unroll
    for (int s = 0; s < STAGES - 1; s++) {
        const uint32_t so = s * PV_STAGE_F * 4;
        const int k0 = s * BK;
        cp16(sE0 + so, gE0 + k0); cp16(sE1 + so, gE1 + k0);
        cp16(sV0 + so, gV0 + (size_t)k0 * DIM); cp16(sV1 + so, gV1 + (size_t)k0 * DIM);
        CP_COMMIT();
    }

    for (int it = 0; it < NT; it++) {
        CP_WAIT1();
        __syncthreads();
        {
            const int tn = it + 2;
            if (tn < NT) {
                const uint32_t so = (tn % STAGES) * PV_STAGE_F * 4;
                const int k0 = tn * BK;
                cp16(sE0 + so, gE0 + k0); cp16(sE1 + so, gE1 + k0);
                cp16(sV0 + so, gV0 + (size_t)k0 * DIM); cp16(sV1 + so, gV1 + (size_t)k0 * DIM);
            }
            CP_COMMIT();
        }
        const float* Es = dsm + (it % STAGES) * PV_STAGE_F;
        const float* Vs = Es + BM * PADK;
        COMPUTE_NM(Es, Vs);
    }

    // Epilogue: scale by 1/den, store.
    #pragma unroll
    for (int mt = 0; mt < 4; mt++) {
        const int rr = rowBase + mBase + mt * 16 + qid;
        const float inv0 = 1.0f / g_den[bS + rr];
        const float inv1 = 1.0f / g_den[bS + rr + 8];
        #pragma unroll
        for (int nt = 0; nt < 4; nt++) {
            const int cc = colBase + nBase + nt * 8 + tq * 2;
            *(float2*)&out[((size_t)bS + rr) * DIM + cc] =
                make_float2(acc[mt][nt][0] * inv0, acc[mt][nt][1] * inv0);
            *(float2*)&out[((size_t)bS + rr + 8) * DIM + cc] =
                make_float2(acc[mt][nt][2] * inv1, acc[mt][nt][3] * inv1);
        }
    }
}

// ---------------------------------------------------------------------------
extern "C" void kernel_launch(void* const* d_in, const int* in_sizes, int n_in,
                              void* d_out, int out_size)
{
    const float* A    = (const float*)d_in[0];
    const int*   mask = (const int*)d_in[1];
    float*       out  = (float*)d_out;

    cudaFuncSetAttribute(qk_exp_mma, cudaFuncAttributeMaxDynamicSharedMemorySize, QK_SMEM);
    cudaFuncSetAttribute(pv_mma,     cudaFuncAttributeMaxDynamicSharedMemorySize, PV_SMEM);

    dim3 g1(SEQ / BN, SEQ / BM, BATCH);   // 8 x 8 x 8
    qk_exp_mma<<<g1, 256, QK_SMEM>>>(A, mask);

    reduce_den_kernel<<<(BATCH * SEQ + 255) / 256, 256>>>();

    dim3 g2(DIM / BN, SEQ / BM, BATCH);   // 6 x 8 x 8
    pv_mma<<<g2, 256, PV_SMEM>>>(A, out);
}

// round 6
// speedup vs baseline: 1.5677x; 1.0549x over previous
#include <cuda_runtime.h>
#include <cstdint>

#define BATCH 8
#define SEQ   1024
#define DIM   768
#define EPS_F 1e-7f

#define BM 128
#define BN 128
#define BK 16
#define PADK 20      // K-major padded k-stride (floats)
#define PADN 136     // N-major padded n-stride (floats): conflict-free V frags
#define STAGES 3

// qk stage: As[128*PADK] + Bs[128*PADK]
#define QK_STAGE_F (2 * BM * PADK)                 // 5120 floats
#define QK_SMEM    (STAGES * QK_STAGE_F * 4)       // 61440 B
// pv stage: Es[128*PADK] + Vs[16*PADN]
#define PV_STAGE_F (BM * PADK + BK * PADN)         // 4736 floats
#define PV_SMEM    (STAGES * PV_STAGE_F * 4)       // 56832 B

// Scratch (allocation-free rule: __device__ globals)
__device__ float g_Atf[(size_t)BATCH * SEQ * DIM];  // tf32-rounded copy of A
__device__ float g_E[(size_t)BATCH * SEQ * SEQ];    // tf32-rounded exp scores
__device__ float g_partial[(size_t)BATCH * SEQ * 32];
__device__ float g_den[(size_t)BATCH * SEQ];

__device__ __forceinline__ uint32_t smem_u32(const void* p) {
    uint32_t a;
    asm("{ .reg .u64 t; cvta.to.shared.u64 t, %1; cvt.u32.u64 %0, t; }" : "=r"(a) : "l"(p));
    return a;
}
__device__ __forceinline__ uint32_t f2tf(float x) {
    uint32_t u; asm("cvt.rna.tf32.f32 %0, %1;" : "=r"(u) : "f"(x)); return u;
}
__device__ __forceinline__ void mma_tf32(float c[4],
                                         uint32_t a0, uint32_t a1, uint32_t a2, uint32_t a3,
                                         uint32_t b0, uint32_t b1) {
    asm("mma.sync.aligned.m16n8k8.row.col.f32.tf32.tf32.f32 "
        "{%0,%1,%2,%3}, {%4,%5,%6,%7}, {%8,%9}, {%0,%1,%2,%3};"
        : "+f"(c[0]), "+f"(c[1]), "+f"(c[2]), "+f"(c[3])
        : "r"(a0), "r"(a1), "r"(a2), "r"(a3), "r"(b0), "r"(b1));
}
__device__ __forceinline__ void cp16(uint32_t saddr, const void* g) {
    asm volatile("cp.async.cg.shared.global [%0], [%1], 16;" :: "r"(saddr), "l"(g));
}
#define CP_COMMIT() asm volatile("cp.async.commit_group;" ::: "memory")
#define CP_WAIT1()  asm volatile("cp.async.wait_group 1;" ::: "memory")

// ---------------------------------------------------------------------------
// Compute cores: block 128x128, 8 warps (2x4), warp tile 64x32 (4x4 m16n8).
// Data in SMEM is pre-rounded tf32 -> pure LDS + HMMA, zero CVT.
// ---------------------------------------------------------------------------
#define COMPUTE_KM(AsBuf, BsBuf)                                              \
    _Pragma("unroll")                                                         \
    for (int ks = 0; ks < 2; ks++) {                                          \
        uint32_t bf[4][2];                                                    \
        _Pragma("unroll")                                                     \
        for (int nt = 0; nt < 4; nt++) {                                      \
            const uint32_t* bp = (const uint32_t*)(BsBuf) +                   \
                (nBase + nt * 8 + qid) * PADK + ks * 8 + tq;                  \
            bf[nt][0] = bp[0]; bf[nt][1] = bp[4];                             \
        }                                                                     \
        _Pragma("unroll")                                                     \
        for (int mt = 0; mt < 4; mt++) {                                      \
            const uint32_t* ap = (const uint32_t*)(AsBuf) +                   \
                (mBase + mt * 16 + qid) * PADK + ks * 8 + tq;                 \
            uint32_t a0 = ap[0];                                              \
            uint32_t a1 = ap[8 * PADK];                                       \
            uint32_t a2 = ap[4];                                              \
            uint32_t a3 = ap[8 * PADK + 4];                                   \
            _Pragma("unroll")                                                 \
            for (int nt = 0; nt < 4; nt++)                                    \
                mma_tf32(acc[mt][nt], a0, a1, a2, a3, bf[nt][0], bf[nt][1]);  \
        }                                                                     \
    }

#define COMPUTE_NM(AsBuf, VsBuf)                                              \
    _Pragma("unroll")                                                         \
    for (int ks = 0; ks < 2; ks++) {                                          \
        uint32_t bf[4][2];                                                    \
        _Pragma("unroll")                                                     \
        for (int nt = 0; nt < 4; nt++) {                                      \
            const uint32_t* bp = (const uint32_t*)(VsBuf) +                   \
                (ks * 8 + tq) * PADN + nBase + nt * 8 + qid;                  \
            bf[nt][0] = bp[0]; bf[nt][1] = bp[4 * PADN];                      \
        }                                                                     \
        _Pragma("unroll")                                                     \
        for (int mt = 0; mt < 4; mt++) {                                      \
            const uint32_t* ap = (const uint32_t*)(AsBuf) +                   \
                (mBase + mt * 16 + qid) * PADK + ks * 8 + tq;                 \
            uint32_t a0 = ap[0];                                              \
            uint32_t a1 = ap[8 * PADK];                                       \
            uint32_t a2 = ap[4];                                              \
            uint32_t a3 = ap[8 * PADK + 4];                                   \
            _Pragma("unroll")                                                 \
            for (int nt = 0; nt < 4; nt++)                                    \
                mma_tf32(acc[mt][nt], a0, a1, a2, a3, bf[nt][0], bf[nt][1]);  \
        }                                                                     \
    }

// ---------------------------------------------------------------------------
// Kernel 0: pre-round A to tf32 once.
// ---------------------------------------------------------------------------
__global__ void __launch_bounds__(256) cvt_kernel(const float* __restrict__ A)
{
    size_t i = ((size_t)blockIdx.x * blockDim.x + threadIdx.x) * 4;
    const size_t N = (size_t)BATCH * SEQ * DIM;
    if (i < N) {
        float4 v = *(const float4*)(A + i);
        uint4 t = make_uint4(f2tf(v.x), f2tf(v.y), f2tf(v.z), f2tf(v.w));
        *(uint4*)(g_Atf + i) = t;
    }
}

// ---------------------------------------------------------------------------
// Kernel 1: E = exp(A A^T) * m_row * m_col + partial row sums.
// ---------------------------------------------------------------------------
__global__ void __launch_bounds__(256, 2) qk_exp_mma(const int* __restrict__ mask)
{
    extern __shared__ float dsm[];

    const int b       = blockIdx.z;
    const int rowBase = blockIdx.y * BM;
    const int colBase = blockIdx.x * BN;
    const float* Ab = g_Atf + (size_t)b * SEQ * DIM;
    const int bS = b * SEQ;

    const int tid  = threadIdx.x;
    const int wid  = tid >> 5;
    const int lane = tid & 31;
    const int qid  = lane >> 2;
    const int tq   = lane & 3;
    const int mBase = (wid >> 2) * 64;
    const int nBase = (wid & 3) * 32;

    const int r0  = tid >> 2;
    const int c4  = (tid & 3) << 2;
    const float* gA0 = Ab + (size_t)(rowBase + r0) * DIM + c4;
    const float* gA1 = gA0 + (size_t)64 * DIM;
    const float* gB0 = Ab + (size_t)(colBase + r0) * DIM + c4;
    const float* gB1 = gB0 + (size_t)64 * DIM;
    const uint32_t sb  = smem_u32(dsm);
    const uint32_t sA0 = sb + (r0 * PADK + c4) * 4;
    const uint32_t sA1 = sb + ((r0 + 64) * PADK + c4) * 4;
    const uint32_t sB0 = sb + (BM * PADK + r0 * PADK + c4) * 4;
    const uint32_t sB1 = sb + (BM * PADK + (r0 + 64) * PADK + c4) * 4;

    float acc[4][4][4];
    #pragma unroll
    for (int i = 0; i < 4; i++)
        #pragma unroll
        for (int j = 0; j < 4; j++)
            #pragma unroll
            for (int k = 0; k < 4; k++) acc[i][j][k] = 0.f;

    const int NT = DIM / BK;   // 48

    #pragma unroll
    for (int s = 0; s < STAGES - 1; s++) {
        const uint32_t so = s * QK_STAGE_F * 4;
        const int k0 = s * BK;
        cp16(sA0 + so, gA0 + k0); cp16(sA1 + so, gA1 + k0);
        cp16(sB0 + so, gB0 + k0); cp16(sB1 + so, gB1 + k0);
        CP_COMMIT();
    }

    for (int it = 0; it < NT; it++) {
        CP_WAIT1();
        __syncthreads();
        {
            const int tn = it + 2;
            if (tn < NT) {
                const uint32_t so = (tn % STAGES) * QK_STAGE_F * 4;
                const int k0 = tn * BK;
                cp16(sA0 + so, gA0 + k0); cp16(sA1 + so, gA1 + k0);
                cp16(sB0 + so, gB0 + k0); cp16(sB1 + so, gB1 + k0);
            }
            CP_COMMIT();
        }
        const float* As = dsm + (it % STAGES) * QK_STAGE_F;
        const float* Bs = As + BM * PADK;
        COMPUTE_KM(As, Bs);
    }

    // Epilogue: exp * masks; store tf32-rounded E; deterministic partials.
    const int wc = wid & 3;
    #pragma unroll
    for (int mt = 0; mt < 4; mt++) {
        const int rr = rowBase + mBase + mt * 16 + qid;
        const float mr0 = (float)mask[bS + rr];
        const float mr1 = (float)mask[bS + rr + 8];
        float s0 = 0.f, s1 = 0.f;
        #pragma unroll
        for (int nt = 0; nt < 4; nt++) {
            const int cc = colBase + nBase + nt * 8 + tq * 2;
            const float mc0 = (float)mask[bS + cc];
            const float mc1 = (float)mask[bS + cc + 1];
            // round to tf32 NOW so pv's fragments need zero conversion
            float e00 = __uint_as_float(f2tf(__expf(acc[mt][nt][0]) * mr0 * mc0));
            float e01 = __uint_as_float(f2tf(__expf(acc[mt][nt][1]) * mr0 * mc1));
            float e10 = __uint_as_float(f2tf(__expf(acc[mt][nt][2]) * mr1 * mc0));
            float e11 = __uint_as_float(f2tf(__expf(acc[mt][nt][3]) * mr1 * mc1));
            s0 += e00 + e01;
            s1 += e10 + e11;
            *(float2*)&g_E[((size_t)bS + rr) * SEQ + cc]     = make_float2(e00, e01);
            *(float2*)&g_E[((size_t)bS + rr + 8) * SEQ + cc] = make_float2(e10, e11);
        }
        s0 += __shfl_xor_sync(0xffffffffu, s0, 1);
        s0 += __shfl_xor_sync(0xffffffffu, s0, 2);
        s1 += __shfl_xor_sync(0xffffffffu, s1, 1);
        s1 += __shfl_xor_sync(0xffffffffu, s1, 2);
        if (tq == 0) {
            g_partial[((size_t)bS + rr) * 32 + blockIdx.x * 4 + wc]     = s0;
            g_partial[((size_t)bS + rr + 8) * 32 + blockIdx.x * 4 + wc] = s1;
        }
    }
}

// ---------------------------------------------------------------------------
__global__ void reduce_den_kernel()
{
    int i = blockIdx.x * blockDim.x + threadIdx.x;
    if (i < BATCH * SEQ) {
        float s = EPS_F;
        #pragma unroll
        for (int j = 0; j < 32; j++) s += g_partial[(size_t)i * 32 + j];
        g_den[i] = s;
    }
}

// ---------------------------------------------------------------------------
// Kernel 3: out = (E @ A) / den.  E and V both pre-rounded; V stage is [k][n].
// ---------------------------------------------------------------------------
__global__ void __launch_bounds__(256, 2) pv_mma(float* __restrict__ out)
{
    extern __shared__ float dsm[];

    const int b       = blockIdx.z;
    const int rowBase = blockIdx.y * BM;   // S rows
    const int colBase = blockIdx.x * BN;   // D cols
    const float* Ab = g_Atf + (size_t)b * SEQ * DIM;
    const float* Eb = g_E   + (size_t)b * SEQ * SEQ;
    const int bS = b * SEQ;

    const int tid  = threadIdx.x;
    const int wid  = tid >> 5;
    const int lane = tid & 31;
    const int qid  = lane >> 2;
    const int tq   = lane & 3;
    const int mBase = (wid >> 2) * 64;
    const int nBase = (wid & 3) * 32;

    const int r0  = tid >> 2;
    const int c4  = (tid & 3) << 2;
    const float* gE0 = Eb + (size_t)(rowBase + r0) * SEQ + c4;
    const float* gE1 = gE0 + (size_t)64 * SEQ;
    const int vr0  = tid >> 5;             // 0..7
    const int vc4  = (tid & 31) << 2;      // 0..124
    const float* gV0 = Ab + (size_t)vr0 * DIM + colBase + vc4;
    const float* gV1 = gV0 + (size_t)8 * DIM;

    const uint32_t sb  = smem_u32(dsm);
    const uint32_t sE0 = sb + (r0 * PADK + c4) * 4;
    const uint32_t sE1 = sb + ((r0 + 64) * PADK + c4) * 4;
    const uint32_t sV0 = sb + (BM * PADK + vr0 * PADN + vc4) * 4;
    const uint32_t sV1 = sb + (BM * PADK + (vr0 + 8) * PADN + vc4) * 4;

    float acc[4][4][4];
    #pragma unroll
    for (int i = 0; i < 4; i++)
        #pragma unroll
        for (int j = 0; j < 4; j++)
            #pragma unroll
            for (int k = 0; k < 4; k++) acc[i][j][k] = 0.f;

    const int NT = SEQ / BK;   // 64

    #pragma unroll
    for (int s = 0; s < STAGES - 1; s++) {
        const uint32_t so = s * PV_STAGE_F * 4;
        const int k0 = s * BK;
        cp16(sE0 + so, gE0 + k0); cp16(sE1 + so, gE1 + k0);
        cp16(sV0 + so, gV0 + (size_t)k0 * DIM); cp16(sV1 + so, gV1 + (size_t)k0 * DIM);
        CP_COMMIT();
    }

    for (int it = 0; it < NT; it++) {
        CP_WAIT1();
        __syncthreads();
        {
            const int tn = it + 2;
            if (tn < NT) {
                const uint32_t so = (tn % STAGES) * PV_STAGE_F * 4;
                const int k0 = tn * BK;
                cp16(sE0 + so, gE0 + k0); cp16(sE1 + so, gE1 + k0);
                cp16(sV0 + so, gV0 + (size_t)k0 * DIM); cp16(sV1 + so, gV1 + (size_t)k0 * DIM);
            }
            CP_COMMIT();
        }
        const float* Es = dsm + (it % STAGES) * PV_STAGE_F;
        const float* Vs = Es + BM * PADK;
        COMPUTE_NM(Es, Vs);
    }

    // Epilogue: scale by 1/den, store.
    #pragma unroll
    for (int mt = 0; mt < 4; mt++) {
        const int rr = rowBase + mBase + mt * 16 + qid;
        const float inv0 = 1.0f / g_den[bS + rr];
        const float inv1 = 1.0f / g_den[bS + rr + 8];
        #pragma unroll
        for (int nt = 0; nt < 4; nt++) {
            const int cc = colBase + nBase + nt * 8 + tq * 2;
            *(float2*)&out[((size_t)bS + rr) * DIM + cc] =
                make_float2(acc[mt][nt][0] * inv0, acc[mt][nt][1] * inv0);
            *(float2*)&out[((size_t)bS + rr + 8) * DIM + cc] =
                make_float2(acc[mt][nt][2] * inv1, acc[mt][nt][3] * inv1);
        }
    }
}

// ---------------------------------------------------------------------------
extern "C" void kernel_launch(void* const* d_in, const int* in_sizes, int n_in,
                              void* d_out, int out_size)
{
    const float* A    = (const float*)d_in[0];
    const int*   mask = (const int*)d_in[1];
    float*       out  = (float*)d_out;

    cudaFuncSetAttribute(qk_exp_mma, cudaFuncAttributeMaxDynamicSharedMemorySize, QK_SMEM);
    cudaFuncSetAttribute(pv_mma,     cudaFuncAttributeMaxDynamicSharedMemorySize, PV_SMEM);

    const size_t nA = (size_t)BATCH * SEQ * DIM;
    cvt_kernel<<<(unsigned)((nA / 4 + 255) / 256), 256>>>(A);

    dim3 g1(SEQ / BN, SEQ / BM, BATCH);   // 8 x 8 x 8
    qk_exp_mma<<<g1, 256, QK_SMEM>>>(mask);

    reduce_den_kernel<<<(BATCH * SEQ + 255) / 256, 256>>>();

    dim3 g2(DIM / BN, SEQ / BM, BATCH);   // 6 x 8 x 8
    pv_mma<<<g2, 256, PV_SMEM>>>(out);
}

// round 7
// speedup vs baseline: 2.1070x; 1.3440x over previous
#include <cuda_runtime.h>
#include <cstdint>

#define BATCH 8
#define SEQ   1024
#define DIM   768
#define EPS_F 1e-7f

#define BM 128
#define BN 128
#define BK 32
#define PADK 36      // K-major padded k-stride (floats): bank = 4*qid+tq+8*ks, conflict-free
#define PADN 136     // N-major padded n-stride (floats)
#define PADT 132     // transpose-stage stride: bank spread 8*tq+qid, conflict-free
#define STAGES 3

// qk stage: As[128*PADK] + Bs[128*PADK]
#define QK_STAGE_F (2 * BM * PADK)                 // 9216 floats
#define QK_SMEM    (STAGES * QK_STAGE_F * 4)       // 110592 B
// pv stage: Es[128*PADK] + Vs[32*PADN]
#define PV_STAGE_F (BM * PADK + BK * PADN)         // 8960 floats
#define PV_SMEM    (STAGES * PV_STAGE_F * 4)       // 107520 B

// Scratch (allocation-free rule: __device__ globals)
__device__ float g_Atf[(size_t)BATCH * SEQ * DIM];  // tf32-rounded copy of A
__device__ float g_E[(size_t)BATCH * SEQ * SEQ];    // tf32-rounded exp scores
__device__ float g_partial[(size_t)BATCH * SEQ * 32];
__device__ float g_den[(size_t)BATCH * SEQ];

__device__ __forceinline__ uint32_t smem_u32(const void* p) {
    uint32_t a;
    asm("{ .reg .u64 t; cvta.to.shared.u64 t, %1; cvt.u32.u64 %0, t; }" : "=r"(a) : "l"(p));
    return a;
}
__device__ __forceinline__ uint32_t f2tf(float x) {
    uint32_t u; asm("cvt.rna.tf32.f32 %0, %1;" : "=r"(u) : "f"(x)); return u;
}
__device__ __forceinline__ void mma_tf32(float c[4],
                                         uint32_t a0, uint32_t a1, uint32_t a2, uint32_t a3,
                                         uint32_t b0, uint32_t b1) {
    asm("mma.sync.aligned.m16n8k8.row.col.f32.tf32.tf32.f32 "
        "{%0,%1,%2,%3}, {%4,%5,%6,%7}, {%8,%9}, {%0,%1,%2,%3};"
        : "+f"(c[0]), "+f"(c[1]), "+f"(c[2]), "+f"(c[3])
        : "r"(a0), "r"(a1), "r"(a2), "r"(a3), "r"(b0), "r"(b1));
}
__device__ __forceinline__ void cp16(uint32_t saddr, const void* g) {
    asm volatile("cp.async.cg.shared.global [%0], [%1], 16;" :: "r"(saddr), "l"(g));
}
#define CP_COMMIT() asm volatile("cp.async.commit_group;" ::: "memory")
#define CP_WAIT1()  asm volatile("cp.async.wait_group 1;" ::: "memory")

// ---------------------------------------------------------------------------
// Compute cores: block 128x128, 8 warps (2x4), warp tile 64x32 (4x4 m16n8),
// BK=32 => 4 k-steps per tile. Pure LDS+HMMA (data pre-rounded to tf32).
// ---------------------------------------------------------------------------
#define COMPUTE_KM(AsBuf, BsBuf)                                              \
    _Pragma("unroll")                                                         \
    for (int ks = 0; ks < 4; ks++) {                                          \
        uint32_t bf[4][2];                                                    \
        _Pragma("unroll")                                                     \
        for (int nt = 0; nt < 4; nt++) {                                      \
            const uint32_t* bp = (const uint32_t*)(BsBuf) +                   \
                (nBase + nt * 8 + qid) * PADK + ks * 8 + tq;                  \
            bf[nt][0] = bp[0]; bf[nt][1] = bp[4];                             \
        }                                                                     \
        _Pragma("unroll")                                                     \
        for (int mt = 0; mt < 4; mt++) {                                      \
            const uint32_t* ap = (const uint32_t*)(AsBuf) +                   \
                (mBase + mt * 16 + qid) * PADK + ks * 8 + tq;                 \
            uint32_t a0 = ap[0];                                              \
            uint32_t a1 = ap[8 * PADK];                                       \
            uint32_t a2 = ap[4];                                              \
            uint32_t a3 = ap[8 * PADK + 4];                                   \
            _Pragma("unroll")                                                 \
            for (int nt = 0; nt < 4; nt++)                                    \
                mma_tf32(acc[mt][nt], a0, a1, a2, a3, bf[nt][0], bf[nt][1]);  \
        }                                                                     \
    }

#define COMPUTE_NM(AsBuf, VsBuf)                                              \
    _Pragma("unroll")                                                         \
    for (int ks = 0; ks < 4; ks++) {                                          \
        uint32_t bf[4][2];                                                    \
        _Pragma("unroll")                                                     \
        for (int nt = 0; nt < 4; nt++) {                                      \
            const uint32_t* bp = (const uint32_t*)(VsBuf) +                   \
                (ks * 8 + tq) * PADN + nBase + nt * 8 + qid;                  \
            bf[nt][0] = bp[0]; bf[nt][1] = bp[4 * PADN];                      \
        }                                                                     \
        _Pragma("unroll")                                                     \
        for (int mt = 0; mt < 4; mt++) {                                      \
            const uint32_t* ap = (const uint32_t*)(AsBuf) +                   \
                (mBase + mt * 16 + qid) * PADK + ks * 8 + tq;                 \
            uint32_t a0 = ap[0];                                              \
            uint32_t a1 = ap[8 * PADK];                                       \
            uint32_t a2 = ap[4];                                              \
            uint32_t a3 = ap[8 * PADK + 4];                                   \
            _Pragma("unroll")                                                 \
            for (int nt = 0; nt < 4; nt++)                                    \
                mma_tf32(acc[mt][nt], a0, a1, a2, a3, bf[nt][0], bf[nt][1]);  \
        }                                                                     \
    }

// ---------------------------------------------------------------------------
// Kernel 0: pre-round A to tf32 once.
// ---------------------------------------------------------------------------
__global__ void __launch_bounds__(256) cvt_kernel(const float* __restrict__ A)
{
    size_t i = ((size_t)blockIdx.x * blockDim.x + threadIdx.x) * 4;
    const size_t N = (size_t)BATCH * SEQ * DIM;
    if (i < N) {
        float4 v = *(const float4*)(A + i);
        uint4 t = make_uint4(f2tf(v.x), f2tf(v.y), f2tf(v.z), f2tf(v.w));
        *(uint4*)(g_Atf + i) = t;
    }
}

// ---------------------------------------------------------------------------
// Kernel 1: E = exp(A A^T) * m_row * m_col, SYMMETRIC: only bx >= by tiles
// computed; off-diagonal tiles also emit the transposed tile (via SMEM stage)
// and column-sum partials so every row's denominator stays complete.
// Partial-slot layout per row (32 slots): for row in block-row i,
//   slots j*4+wc (j >= i) <- direct row sums from block (i,j)
//   slots j*4+{0,1} (j < i) <- transposed col sums from block (j,i); {2,3} zeroed
// ---------------------------------------------------------------------------
__global__ void __launch_bounds__(256, 2) qk_exp_mma(const int* __restrict__ mask)
{
    extern __shared__ float dsm[];

    const int bx = blockIdx.x;   // column block
    const int by = blockIdx.y;   // row block
    if (bx < by) return;         // symmetry: upper triangle only
    const bool offdiag = (bx > by);

    const int b       = blockIdx.z;
    const int rowBase = by * BM;
    const int colBase = bx * BN;
    const float* Ab = g_Atf + (size_t)b * SEQ * DIM;
    const int bS = b * SEQ;

    const int tid  = threadIdx.x;
    const int wid  = tid >> 5;
    const int lane = tid & 31;
    const int qid  = lane >> 2;
    const int tq   = lane & 3;
    const int mBase = (wid >> 2) * 64;
    const int nBase = (wid & 3) * 32;
    const int wr   = wid >> 2;   // warp row (0/1)
    const int wc   = wid & 3;    // warp col

    const uint32_t sb = smem_u32(dsm);

    float acc[4][4][4];
    #pragma unroll
    for (int i = 0; i < 4; i++)
        #pragma unroll
        for (int j = 0; j < 4; j++)
            #pragma unroll
            for (int k = 0; k < 4; k++) acc[i][j][k] = 0.f;

    const int NT = DIM / BK;   // 24

    #pragma unroll
    for (int s = 0; s < STAGES - 1; s++) {
        const uint32_t so = s * QK_STAGE_F * 4;
        const int k0 = s * BK;
        #pragma unroll
        for (int l = 0; l < 4; l++) {
            int idx = tid + l * 256;
            int r   = idx >> 3;
            int c4  = (idx & 7) << 2;
            cp16(sb + so + (r * PADK + c4) * 4,
                 Ab + (size_t)(rowBase + r) * DIM + k0 + c4);
            cp16(sb + so + (BM * PADK + r * PADK + c4) * 4,
                 Ab + (size_t)(colBase + r) * DIM + k0 + c4);
        }
        CP_COMMIT();
    }

    for (int it = 0; it < NT; it++) {
        CP_WAIT1();
        __syncthreads();
        {
            const int tn = it + 2;
            if (tn < NT) {
                const uint32_t so = (tn % STAGES) * QK_STAGE_F * 4;
                const int k0 = tn * BK;
                #pragma unroll
                for (int l = 0; l < 4; l++) {
                    int idx = tid + l * 256;
                    int r   = idx >> 3;
                    int c4  = (idx & 7) << 2;
                    cp16(sb + so + (r * PADK + c4) * 4,
                         Ab + (size_t)(rowBase + r) * DIM + k0 + c4);
                    cp16(sb + so + (BM * PADK + r * PADK + c4) * 4,
                         Ab + (size_t)(colBase + r) * DIM + k0 + c4);
                }
            }
            CP_COMMIT();
        }
        const float* As = dsm + (it % STAGES) * QK_STAGE_F;
        const float* Bs = As + BM * PADK;
        COMPUTE_KM(As, Bs);
    }

    __syncthreads();   // pipeline stages are dead; safe to reuse as transpose stage
    float* stage = dsm;          // [128 cols][PADT rows] for off-diag transpose

    float cs[4][2];
    #pragma unroll
    for (int nt = 0; nt < 4; nt++) { cs[nt][0] = 0.f; cs[nt][1] = 0.f; }

    #pragma unroll
    for (int mt = 0; mt < 4; mt++) {
        const int rrl = mBase + mt * 16 + qid;       // local row 0..127
        const int rr  = rowBase + rrl;
        const float mr0 = (float)mask[bS + rr];
        const float mr1 = (float)mask[bS + rr + 8];
        float s0 = 0.f, s1 = 0.f;
        #pragma unroll
        for (int nt = 0; nt < 4; nt++) {
            const int ccl = nBase + nt * 8 + tq * 2; // local col 0..127
            const int cc  = colBase + ccl;
            const float mc0 = (float)mask[bS + cc];
            const float mc1 = (float)mask[bS + cc + 1];
            float e00 = __uint_as_float(f2tf(__expf(acc[mt][nt][0]) * mr0 * mc0));
            float e01 = __uint_as_float(f2tf(__expf(acc[mt][nt][1]) * mr0 * mc1));
            float e10 = __uint_as_float(f2tf(__expf(acc[mt][nt][2]) * mr1 * mc0));
            float e11 = __uint_as_float(f2tf(__expf(acc[mt][nt][3]) * mr1 * mc1));
            s0 += e00 + e01;
            s1 += e10 + e11;
            *(float2*)&g_E[((size_t)bS + rr) * SEQ + cc]     = make_float2(e00, e01);
            *(float2*)&g_E[((size_t)bS + rr + 8) * SEQ + cc] = make_float2(e10, e11);
            if (offdiag) {
                cs[nt][0] += e00 + e10;
                cs[nt][1] += e01 + e11;
                stage[ccl * PADT + rrl]           = e00;
                stage[(ccl + 1) * PADT + rrl]     = e01;
                stage[ccl * PADT + rrl + 8]       = e10;
                stage[(ccl + 1) * PADT + rrl + 8] = e11;
            }
        }
        s0 += __shfl_xor_sync(0xffffffffu, s0, 1);
        s0 += __shfl_xor_sync(0xffffffffu, s0, 2);
        s1 += __shfl_xor_sync(0xffffffffu, s1, 1);
        s1 += __shfl_xor_sync(0xffffffffu, s1, 2);
        if (tq == 0) {
            g_partial[((size_t)bS + rr) * 32 + bx * 4 + wc]     = s0;
            g_partial[((size_t)bS + rr + 8) * 32 + bx * 4 + wc] = s1;
        }
    }

    if (offdiag) {
        // column-sum partials: reduce over qid lanes (xor 4,8,16)
        #pragma unroll
        for (int nt = 0; nt < 4; nt++) {
            #pragma unroll
            for (int h = 0; h < 2; h++) {
                float v = cs[nt][h];
                v += __shfl_xor_sync(0xffffffffu, v, 4);
                v += __shfl_xor_sync(0xffffffffu, v, 8);
                v += __shfl_xor_sync(0xffffffffu, v, 16);
                cs[nt][h] = v;
            }
        }
        if (qid == 0) {   // lanes 0..3 (lane == tq)
            #pragma unroll
            for (int nt = 0; nt < 4; nt++) {
                const int cc = colBase + nBase + nt * 8 + tq * 2;
                g_partial[((size_t)bS + cc) * 32 + by * 4 + wr]         = cs[nt][0];
                g_partial[((size_t)bS + cc + 1) * 32 + by * 4 + wr]     = cs[nt][1];
                g_partial[((size_t)bS + cc) * 32 + by * 4 + 2 + wr]     = 0.f;
                g_partial[((size_t)bS + cc + 1) * 32 + by * 4 + 2 + wr] = 0.f;
            }
        }
        __syncthreads();
        // coalesced transposed-tile store: E[colBase+c][rowBase+r]
        #pragma unroll
        for (int l = 0; l < 16; l++) {
            int idx = tid + l * 256;      // 0..4095
            int c   = idx >> 5;           // 0..127
            int r4  = (idx & 31) << 2;    // 0..124
            float4 v = *(float4*)&stage[c * PADT + r4];
            *(float4*)&g_E[((size_t)bS + colBase + c) * SEQ + rowBase + r4] = v;
        }
    }
}

// ---------------------------------------------------------------------------
__global__ void reduce_den_kernel()
{
    int i = blockIdx.x * blockDim.x + threadIdx.x;
    if (i < BATCH * SEQ) {
        float s = EPS_F;
        #pragma unroll
        for (int j = 0; j < 32; j++) s += g_partial[(size_t)i * 32 + j];
        g_den[i] = s;
    }
}

// ---------------------------------------------------------------------------
// Kernel 3: out = (E @ A) / den.  BK=32; V stage is [k][n].
// ---------------------------------------------------------------------------
__global__ void __launch_bounds__(256, 2) pv_mma(float* __restrict__ out)
{
    extern __shared__ float dsm[];

    const int b       = blockIdx.z;
    const int rowBase = blockIdx.y * BM;   // S rows
    const int colBase = blockIdx.x * BN;   // D cols
    const float* Ab = g_Atf + (size_t)b * SEQ * DIM;
    const float* Eb = g_E   + (size_t)b * SEQ * SEQ;
    const int bS = b * SEQ;

    const int tid  = threadIdx.x;
    const int wid  = tid >> 5;
    const int lane = tid & 31;
    const int qid  = lane >> 2;
    const int tq   = lane & 3;
    const int mBase = (wid >> 2) * 64;
    const int nBase = (wid & 3) * 32;

    const uint32_t sb = smem_u32(dsm);

    float acc[4][4][4];
    #pragma unroll
    for (int i = 0; i < 4; i++)
        #pragma unroll
        for (int j = 0; j < 4; j++)
            #pragma unroll
            for (int k = 0; k < 4; k++) acc[i][j][k] = 0.f;

    const int NT = SEQ / BK;   // 32

    #pragma unroll
    for (int s = 0; s < STAGES - 1; s++) {
        const uint32_t so = s * PV_STAGE_F * 4;
        const int k0 = s * BK;
        #pragma unroll
        for (int l = 0; l < 4; l++) {
            int idx = tid + l * 256;
            int r   = idx >> 3;
            int c4  = (idx & 7) << 2;
            cp16(sb + so + (r * PADK + c4) * 4,
                 Eb + (size_t)(rowBase + r) * SEQ + k0 + c4);
            int vr  = idx >> 5;
            int vc4 = (idx & 31) << 2;
            cp16(sb + so + (BM * PADK + vr * PADN + vc4) * 4,
                 Ab + (size_t)(k0 + vr) * DIM + colBase + vc4);
        }
        CP_COMMIT();
    }

    for (int it = 0; it < NT; it++) {
        CP_WAIT1();
        __syncthreads();
        {
            const int tn = it + 2;
            if (tn < NT) {
                const uint32_t so = (tn % STAGES) * PV_STAGE_F * 4;
                const int k0 = tn * BK;
                #pragma unroll
                for (int l = 0; l < 4; l++) {
                    int idx = tid + l * 256;
                    int r   = idx >> 3;
                    int c4  = (idx & 7) << 2;
                    cp16(sb + so + (r * PADK + c4) * 4,
                         Eb + (size_t)(rowBase + r) * SEQ + k0 + c4);
                    int vr  = idx >> 5;
                    int vc4 = (idx & 31) << 2;
                    cp16(sb + so + (BM * PADK + vr * PADN + vc4) * 4,
                         Ab + (size_t)(k0 + vr) * DIM + colBase + vc4);
                }
            }
            CP_COMMIT();
        }
        const float* Es = dsm + (it % STAGES) * PV_STAGE_F;
        const float* Vs = Es + BM * PADK;
        COMPUTE_NM(Es, Vs);
    }

    // Epilogue: scale by 1/den, store.
    #pragma unroll
    for (int mt = 0; mt < 4; mt++) {
        const int rr = rowBase + mBase + mt * 16 + qid;
        const float inv0 = 1.0f / g_den[bS + rr];
        const float inv1 = 1.0f / g_den[bS + rr + 8];
        #pragma unroll
        for (int nt = 0; nt < 4; nt++) {
            const int cc = colBase + nBase + nt * 8 + tq * 2;
            *(float2*)&out[((size_t)bS + rr) * DIM + cc] =
                make_float2(acc[mt][nt][0] * inv0, acc[mt][nt][1] * inv0);
            *(float2*)&out[((size_t)bS + rr + 8) * DIM + cc] =
                make_float2(acc[mt][nt][2] * inv1, acc[mt][nt][3] * inv1);
        }
    }
}

// ---------------------------------------------------------------------------
extern "C" void kernel_launch(void* const* d_in, const int* in_sizes, int n_in,
                              void* d_out, int out_size)
{
    const float* A    = (const float*)d_in[0];
    const int*   mask = (const int*)d_in[1];
    float*       out  = (float*)d_out;

    cudaFuncSetAttribute(qk_exp_mma, cudaFuncAttributeMaxDynamicSharedMemorySize, QK_SMEM);
    cudaFuncSetAttribute(pv_mma,     cudaFuncAttributeMaxDynamicSharedMemorySize, PV_SMEM);

    const size_t nA = (size_t)BATCH * SEQ * DIM;
    cvt_kernel<<<(unsigned)((nA / 4 + 255) / 256), 256>>>(A);

    dim3 g1(SEQ / BN, SEQ / BM, BATCH);   // 8 x 8 x 8 (lower triangle exits early)
    qk_exp_mma<<<g1, 256, QK_SMEM>>>(mask);

    reduce_den_kernel<<<(BATCH * SEQ + 255) / 256, 256>>>();

    dim3 g2(DIM / BN, SEQ / BM, BATCH);   // 6 x 8 x 8
    pv_mma<<<g2, 256, PV_SMEM>>>(out);
}